// round 15
// baseline (speedup 1.0000x reference)
#include <cuda_runtime.h>
#include <cuda_bf16.h>
#include <cuda_fp16.h>

#define CH 3
#define IH 4096
#define IW 4096
#define TILES 8
#define TSZ 512                 // tile height/width
#define NTILES (CH * TILES * TILES)   // 192
#define NCHUNK 8                // row-chunks (blocks) per tile in hist pass
#define AREA (TSZ * TSZ)        // 262144
#define CLIPF 1228.0f           // int(1.2 * 262144 / 256) = 1228

// Scratch (allocation-free rule: __device__ globals)
__device__ unsigned char g_v[CH * IH * IW];             // 50.3 MB quantized values
__device__ unsigned int  g_part[NTILES * NCHUNK * 256]; // per-block partial hists
__device__ float         g_lut[NTILES * 256];           // per-tile LUTs

// ---------------------------------------------------------------------------
// 1536 blocks: 8 row-chunks (64 rows each) per tile, 192 tiles.
// Unrolled x2: two independent float4 loads in flight per iteration (MLP up).
// img read with __ldcs (streaming, read-once) so g_v can stay L2-resident.
__global__ __launch_bounds__(256) void hist_kernel(const float* __restrict__ img) {
    __shared__ unsigned int sh[8][256];     // per-warp sub-histograms
    const int tid  = threadIdx.x;
    const int warp = tid >> 5;

    #pragma unroll
    for (int i = tid; i < 8 * 256; i += 256)
        ((unsigned int*)sh)[i] = 0u;
    __syncthreads();

    const int b     = blockIdx.x;       // 0..1535
    const int chunk = b & 7;
    const int tile  = b >> 3;           // 0..191
    const int c     = tile / (TILES * TILES);
    const int t     = tile % (TILES * TILES);
    const int ty    = t >> 3;
    const int tx    = t & 7;
    const int ybase = ty * TSZ + chunk * 64;
    const int xbase = tx * TSZ;

    // 8192 float4s per block; 256 threads × 16 iters × 2 f4s
    for (int i = tid; i < 64 * 128; i += 512) {
        const int i2 = i + 256;
        const int ya = ybase + (i  >> 7), xa = xbase + ((i  & 127) << 2);
        const int yb = ybase + (i2 >> 7), xb2 = xbase + ((i2 & 127) << 2);
        const size_t offa = ((size_t)c << 24) + ((size_t)ya << 12) + (size_t)xa;
        const size_t offb = ((size_t)c << 24) + ((size_t)yb << 12) + (size_t)xb2;
        const float4 pa = __ldcs((const float4*)(img + offa));
        const float4 pb = __ldcs((const float4*)(img + offb));

        int a0 = min(max((int)(pa.x * 255.0f), 0), 255);
        int a1 = min(max((int)(pa.y * 255.0f), 0), 255);
        int a2 = min(max((int)(pa.z * 255.0f), 0), 255);
        int a3 = min(max((int)(pa.w * 255.0f), 0), 255);
        int b0 = min(max((int)(pb.x * 255.0f), 0), 255);
        int b1 = min(max((int)(pb.y * 255.0f), 0), 255);
        int b2 = min(max((int)(pb.z * 255.0f), 0), 255);
        int b3 = min(max((int)(pb.w * 255.0f), 0), 255);

        atomicAdd(&sh[warp][a0], 1u);
        atomicAdd(&sh[warp][a1], 1u);
        atomicAdd(&sh[warp][a2], 1u);
        atomicAdd(&sh[warp][a3], 1u);
        atomicAdd(&sh[warp][b0], 1u);
        atomicAdd(&sh[warp][b1], 1u);
        atomicAdd(&sh[warp][b2], 1u);
        atomicAdd(&sh[warp][b3], 1u);

        uchar4 ua, ub;
        ua.x = (unsigned char)a0; ua.y = (unsigned char)a1;
        ua.z = (unsigned char)a2; ua.w = (unsigned char)a3;
        ub.x = (unsigned char)b0; ub.y = (unsigned char)b1;
        ub.z = (unsigned char)b2; ub.w = (unsigned char)b3;
        *(uchar4*)(g_v + offa) = ua;
        *(uchar4*)(g_v + offb) = ub;
    }
    __syncthreads();

    unsigned int s = 0;
    #pragma unroll
    for (int w = 0; w < 8; w++) s += sh[w][tid];
    g_part[b * 256 + tid] = s;          // plain store — no atomics, no pre-zero
}

// ---------------------------------------------------------------------------
// One block per tile, 256 threads (one per bin): sum 8 partials, clip,
// redistribute, scan, scale.
__global__ __launch_bounds__(256) void lut_kernel() {
    __shared__ float red[256];
    __shared__ float sc[256];
    const int tile = blockIdx.x;
    const int t    = threadIdx.x;

    unsigned int hsum = 0;
    #pragma unroll
    for (int k = 0; k < NCHUNK; k++)
        hsum += g_part[(tile * NCHUNK + k) * 256 + t];

    const float h  = (float)hsum;
    float cl       = fminf(h, CLIPF);
    const float ex = h - cl;

    red[t] = ex;
    __syncthreads();
    #pragma unroll
    for (int s = 128; s > 0; s >>= 1) {
        if (t < s) red[t] += red[t + s];
        __syncthreads();
    }
    const float excess = red[0];
    cl += excess * (1.0f / 256.0f);

    // inclusive Hillis-Steele scan (fp32)
    sc[t] = cl;
    __syncthreads();
    #pragma unroll
    for (int off = 1; off < 256; off <<= 1) {
        const float val = (t >= off) ? sc[t - off] : 0.0f;
        __syncthreads();
        sc[t] += val;
        __syncthreads();
    }
    const float cdf = sc[t];
    const float scale = (float)(255.0 / (double)AREA);
    float lut = rintf(cdf * scale);           // round-half-even, matches jnp.round
    lut = fminf(fmaxf(lut, 0.0f), 255.0f);
    g_lut[tile * 256 + t] = lut;
}

// ---------------------------------------------------------------------------
// Apply pass, v5: one block per image ROW (4096 px, 16 px/thread).
// c0 = 0 → j0 = x0 directly; all 8 x-tile pair-columns in a 4 KB half2 table.
// x0 transitions at x ≡ 256 (mod 512) — multiple of 16 — so x0 is constant
// within each thread's aligned 16-px group and ax is affine & exact (2^-9 grid).
// Per thread: 1 LDG.128 (16 v-bytes), 16 LDS.32 gathers, 4 streaming STG.128.
__global__ __launch_bounds__(256) void apply_kernel(float* __restrict__ out) {
    __shared__ __half2 Lp[8][256];

    const int bi   = blockIdx.x;                        // row index 0..12287
    const int tid  = threadIdx.x;
    const int c    = bi >> 12;
    const int y    = bi & 0xFFF;
    const size_t pbase = (size_t)bi << 12;              // 4096 px per row

    // y interpolation (block-uniform)
    const float fy = ((float)y + 0.5f) * (1.0f / (float)TSZ) - 0.5f;
    int y0 = (int)floorf(fy);
    y0 = min(max(y0, 0), TILES - 1);
    const float ay = fminf(fmaxf(fy - (float)y0, 0.0f), 1.0f);
    const int y1 = min(y0 + 1, TILES - 1);

    const float* __restrict__ base0 = g_lut + (size_t)((c * TILES + y0) * TILES) * 256;
    const float* __restrict__ base1 = g_lut + (size_t)((c * TILES + y1) * TILES) * 256;
    const float w1 = ay * (1.0f / 255.0f);
    const float w0 = (1.0f - ay) * (1.0f / 255.0f);

    // build 8 y-pre-blended columns, pair with right neighbor (clamped)
    float colv[8];
    #pragma unroll
    for (int j = 0; j < 8; j++)
        colv[j] = w0 * __ldg(base0 + j * 256 + tid) + w1 * __ldg(base1 + j * 256 + tid);
    #pragma unroll
    for (int j = 0; j < 8; j++)
        Lp[j][tid] = __floats2half2_rn(colv[j], colv[min(j + 1, 7)]);
    __syncthreads();

    // this thread's 16 pixels (aligned-16 group → x0 constant, ax affine)
    const int x = tid << 4;
    const float fx = ((float)x + 0.5f) * (1.0f / (float)TSZ) - 0.5f;
    int x0 = (int)floorf(fx);
    x0 = min(max(x0, 0), TILES - 1);
    const float axb = fx - (float)x0;                   // <0 only in first half-tile
    const __half2* __restrict__ Lrow = Lp[x0];

    const size_t p = pbase + ((size_t)tid << 4);
    const uint4 uv = *(const uint4*)(g_v + p);          // 16 quantized bytes
    const unsigned int words[4] = {uv.x, uv.y, uv.z, uv.w};

    float r[16];
    #pragma unroll
    for (int e = 0; e < 16; e++) {
        const int v = (words[e >> 2] >> ((e & 3) * 8)) & 0xFF;
        const float2 g = __half22float2(Lrow[v]);
        const float ax = fmaxf(axb + (float)e * (1.0f / (float)TSZ), 0.0f);
        r[e] = g.x + (g.y - g.x) * ax;
    }
    float4* o = (float4*)(out + p);
    __stcs(o + 0, make_float4(r[0],  r[1],  r[2],  r[3]));
    __stcs(o + 1, make_float4(r[4],  r[5],  r[6],  r[7]));
    __stcs(o + 2, make_float4(r[8],  r[9],  r[10], r[11]));
    __stcs(o + 3, make_float4(r[12], r[13], r[14], r[15]));
}

// ---------------------------------------------------------------------------
extern "C" void kernel_launch(void* const* d_in, const int* in_sizes, int n_in,
                              void* d_out, int out_size) {
    const float* img = (const float*)d_in[0];
    float* out = (float*)d_out;

    hist_kernel<<<NTILES * NCHUNK, 256>>>(img);
    lut_kernel<<<NTILES, 256>>>();
    apply_kernel<<<CH * IH, 256>>>(out);    // one block per row
}